// round 12
// baseline (speedup 1.0000x reference)
#include <cuda_runtime.h>
#include <cuda_fp16.h>
#include <cstdint>

// ---------------------------------------------------------------------------
// MultiHeadAttention on GB300 (sm_103a) — legacy mma.sync fp16, 1-term GEMMs.
// R12: softmax fused into the PV kernel (attn_pv): phase A computes per-row
// max/sum from fp16 scores; phase B regenerates P = exp(s-m)/sum per 32-k
// stage, writes fp32 weights (required output), stages fp16 P in SMEM, and
// runs the PV MMA against a cp.async Vt ring. Eliminates the P fp16
// round-trip (536 MB) and the separate softmax launch.
// ---------------------------------------------------------------------------

using f16 = __half;

static constexpr long long QKV_ELEMS = 8LL * 1024 * 2048;    // 16,777,216
static constexpr long long W_ELEMS   = 128LL * 1024 * 1024;  // 134,217,728
static constexpr long long WW_ELEMS  = 2048LL * 2048;        // 4,194,304

__device__ f16 g_xq[QKV_ELEMS], g_xk[QKV_ELEMS], g_xv[QKV_ELEMS];
__device__ f16 g_wq[WW_ELEMS], g_wk[WW_ELEMS], g_wv[WW_ELEMS], g_wo[WW_ELEMS];
__device__ f16 g_Qh[QKV_ELEMS], g_Kh[QKV_ELEMS], g_Vh[QKV_ELEMS];
__device__ f16 g_Vth[QKV_ELEMS];
__device__ f16 g_P[W_ELEMS];          // fp16 scaled scores
__device__ f16 g_Ah[QKV_ELEMS];
__device__ float g_WS[W_ELEMS];       // fallback weights if d_out lacks tail

// ------------------------- asm helpers --------------------------------------

__device__ __forceinline__ uint32_t smem_u32(const void* p) {
    uint32_t a;
    asm("{ .reg .u64 t; cvta.to.shared.u64 t, %1; cvt.u32.u64 %0, t; }"
        : "=r"(a) : "l"(p));
    return a;
}

__device__ __forceinline__ void cp16(uint32_t dst, const void* src) {
    asm volatile("cp.async.cg.shared.global [%0], [%1], 16;"
                 :: "r"(dst), "l"(src));
}

__device__ __forceinline__ void ldm_x4(uint32_t* r, uint32_t addr) {
    asm volatile("ldmatrix.sync.aligned.m8n8.x4.shared.b16 {%0,%1,%2,%3}, [%4];"
                 : "=r"(r[0]), "=r"(r[1]), "=r"(r[2]), "=r"(r[3]) : "r"(addr));
}

__device__ __forceinline__ void mma16816(float* c, const uint32_t* a,
                                         uint32_t b0, uint32_t b1) {
    asm volatile(
        "mma.sync.aligned.m16n8k16.row.col.f32.f16.f16.f32 "
        "{%0,%1,%2,%3}, {%4,%5,%6,%7}, {%8,%9}, {%0,%1,%2,%3};"
        : "+f"(c[0]), "+f"(c[1]), "+f"(c[2]), "+f"(c[3])
        : "r"(a[0]), "r"(a[1]), "r"(a[2]), "r"(a[3]), "r"(b0), "r"(b1));
}

__device__ __forceinline__ uint32_t round2h(float v0, float v1) {
    return (uint32_t)__half_as_ushort(__float2half_rn(v0)) |
           ((uint32_t)__half_as_ushort(__float2half_rn(v1)) << 16);
}

__device__ __forceinline__ uint32_t swz(int row, int cq) {
    return (uint32_t)(row * 64 + ((cq ^ ((row >> 1) & 3)) << 4));
}

// ------------------------- GEMM ---------------------------------------------
// NT: C[m,n] = sum_k A[m,k] * B[n,k], K-major fp16, 1 MMA term.
// CTA tile 128x128, 8 warps of 32x64, occupancy 2, 5-buffer cp.async ring.
// EPI: 0 = fused QKV (3-way select, f16+bias) | 1 = f16*scale | 3 = f32+bias

#define TILE8K 8192
#define STAGE  16384
#define NBUF   5
#define SMEM_TOTAL 81920

template <int EPI>
__global__ __launch_bounds__(256, 2)
void gemm_mma(const f16* __restrict__ A0, const f16* __restrict__ A1,
              const f16* __restrict__ A2,
              const f16* __restrict__ B0, const f16* __restrict__ B1,
              const f16* __restrict__ B2,
              const float* __restrict__ bias0, const float* __restrict__ bias1,
              const float* __restrict__ bias2,
              float* __restrict__ Cf,
              f16* __restrict__ C0, f16* __restrict__ C1, f16* __restrict__ C2,
              int K, int lda, int ldb, int ldc,
              long long sA, long long sB, long long sC, float scale)
{
    extern __shared__ char smem[];
    const uint32_t sb = smem_u32(smem);
    const int tid = threadIdx.x;
    const int wid = tid >> 5;
    const int lane = tid & 31;
    const int warpM = wid >> 1;
    const int warpN = wid & 1;

    const int m0 = blockIdx.y * 128;
    const int n0g = blockIdx.x * 128;

    const f16* A;
    const f16* B;
    const float* bias;
    f16* Ch;
    int n0;
    if (EPI == 0) {
        const int sel = n0g >> 11;       // 0:Q 1:K 2:V
        n0 = n0g & 2047;
        A    = (sel == 0) ? A0 : (sel == 1) ? A1 : A2;
        B    = (sel == 0) ? B0 : (sel == 1) ? B1 : B2;
        bias = (sel == 0) ? bias0 : (sel == 1) ? bias1 : bias2;
        Ch   = (sel == 0) ? C0 : (sel == 1) ? C1 : C2;
    } else {
        const long long z = blockIdx.z;
        n0 = n0g;
        A = A0 + z * sA;
        B = B0 + z * sB;
        bias = bias0;
        Ch = (EPI == 3) ? nullptr : C0 + z * sC;
        if (EPI == 3) Cf += z * sC;
    }

    const int NS = K >> 5;
    const int lrow = tid >> 1;
    const int lcq0 = (tid & 1) * 2;

    auto issue_stage = [&](int s, int buf) {
        const int k0 = s << 5;
        const uint32_t base = sb + buf * STAGE;
        #pragma unroll
        for (int t = 0; t < 2; t++) {
            const int cq = lcq0 + t;
            const uint32_t so = swz(lrow, cq);
            cp16(base + so, A + (size_t)(m0 + lrow) * lda + k0 + cq * 8);
            cp16(base + TILE8K + so, B + (size_t)(n0 + lrow) * ldb + k0 + cq * 8);
        }
        asm volatile("cp.async.commit_group;");
    };

    float acc[2][8][4];
    #pragma unroll
    for (int mt = 0; mt < 2; mt++)
        #pragma unroll
        for (int nt = 0; nt < 8; nt++)
            #pragma unroll
            for (int j = 0; j < 4; j++)
                acc[mt][nt][j] = 0.f;

    const int frow = lane & 15;
    const int fhi  = lane >> 4;

    #pragma unroll
    for (int i = 0; i < 4; i++) {
        if (i < NS) issue_stage(i, i);
        else asm volatile("cp.async.commit_group;");
    }

    int buf = 0;
    for (int s = 0; s < NS; s++) {
        asm volatile("cp.async.wait_group 3;");
        __syncthreads();
        {
            const int nb = (buf + 4 >= NBUF) ? buf - 1 : buf + 4;
            if (s + 4 < NS) issue_stage(s + 4, nb);
            else asm volatile("cp.async.commit_group;");
        }

        const uint32_t stb = sb + buf * STAGE;
        #pragma unroll
        for (int kq = 0; kq < 2; kq++) {
            uint32_t aH[2][4];
            #pragma unroll
            for (int mt = 0; mt < 2; mt++) {
                const int row = warpM * 32 + mt * 16 + frow;
                ldm_x4(aH[mt], stb + swz(row, kq * 2 + fhi));
            }
            #pragma unroll
            for (int half = 0; half < 2; half++) {
                uint32_t bH[2][4];
                #pragma unroll
                for (int g = 0; g < 2; g++) {
                    const int row = warpN * 64 + (half * 2 + g) * 16 + frow;
                    ldm_x4(bH[g], stb + TILE8K + swz(row, kq * 2 + fhi));
                }
                #pragma unroll
                for (int mt = 0; mt < 2; mt++)
                    #pragma unroll
                    for (int t4 = 0; t4 < 4; t4++) {
                        const int g = t4 >> 1, rs = t4 & 1;
                        mma16816(acc[mt][half * 4 + t4], aH[mt],
                                 bH[g][rs], bH[g][rs + 2]);
                    }
            }
        }
        if (++buf == NBUF) buf = 0;
    }
    __syncthreads();

    // epilogue
    {
        const int PITCH = 132;
        float* st = (float*)smem;
        const int tr = lane >> 2;
        const int tc = (lane & 3) * 2;
        #pragma unroll
        for (int mt = 0; mt < 2; mt++)
            #pragma unroll
            for (int nt = 0; nt < 8; nt++) {
                const int r0 = warpM * 32 + mt * 16 + tr;
                const int c0 = warpN * 64 + nt * 8 + tc;
                st[r0 * PITCH + c0]           = acc[mt][nt][0];
                st[r0 * PITCH + c0 + 1]       = acc[mt][nt][1];
                st[(r0 + 8) * PITCH + c0]     = acc[mt][nt][2];
                st[(r0 + 8) * PITCH + c0 + 1] = acc[mt][nt][3];
            }
        __syncthreads();

        const int orow = tid >> 1;
        const int ocb  = (tid & 1) * 64;
        const float* src = st + orow * PITCH + ocb;
        const size_t cbase = (size_t)(m0 + orow) * ldc + n0 + ocb;

        if (EPI == 3) {
            #pragma unroll
            for (int j = 0; j < 64; j += 4) {
                float4 v = *(const float4*)(src + j);
                const float4 b = *(const float4*)(bias + n0 + ocb + j);
                v.x += b.x; v.y += b.y; v.z += b.z; v.w += b.w;
                *(float4*)(Cf + cbase + j) = v;
            }
        } else if (EPI == 0) {
            #pragma unroll
            for (int j = 0; j < 64; j += 2) {
                const float v0 = src[j] + bias[n0 + ocb + j];
                const float v1 = src[j + 1] + bias[n0 + ocb + j + 1];
                *(uint32_t*)(Ch + cbase + j) = round2h(v0, v1);
            }
        } else {  // EPI == 1
            #pragma unroll
            for (int j = 0; j < 64; j += 2)
                *(uint32_t*)(Ch + cbase + j) =
                    round2h(src[j] * scale, src[j + 1] * scale);
        }
    }
}

// ------------------------- fused softmax + PV --------------------------------
// Per CTA: slab z = blockIdx.z, q-block m0 = blockIdx.y*128.
// Phase A: per-row max & sum over fp16 scores (warp-per-row, 16 rows/warp).
// Phase B: 32 stages of k=32; regenerate P tile = exp(s-m)*inv, write fp32
// weights, stage fp16 P to SMEM (double-buffered), MMA vs cp.async Vt ring.

#define PV_NS 32
#define PV_RING 40960           // 5 x 8KB Vt ring at [0, 40960)
#define PV_PBUF 40960           // 2 x 8KB P tiles at [40960, 57344)
#define PV_MOFF 57344           // m[128], inv[128] at [57344, 58368)
#define PV_SMEM 69632           // epilogue staging needs 67.6KB

__global__ __launch_bounds__(256, 2)
void attn_pv(const f16* __restrict__ S, const f16* __restrict__ Vt,
             float* __restrict__ wf, f16* __restrict__ Oh)
{
    extern __shared__ char smem[];
    const uint32_t sb = smem_u32(smem);
    const int tid = threadIdx.x;
    const int wid = tid >> 5;
    const int lane = tid & 31;
    const int warpM = wid >> 1;
    const int warpN = wid & 1;

    const long long z = blockIdx.z;
    const int m0 = blockIdx.y * 128;
    S  += z * 1048576LL + (long long)m0 * 1024;
    wf += z * 1048576LL + (long long)m0 * 1024;
    Vt += z * 131072LL;
    Oh += z * 131072LL + (long long)m0 * 128;

    const int lrow = tid >> 1;
    const int lcq0 = (tid & 1) * 2;

    // Vt ring prologue (issue early; latency hidden under phase A)
    auto issue_vt = [&](int s, int b) {
        const int k0 = s << 5;
        const uint32_t base = sb + b * 8192;
        #pragma unroll
        for (int t = 0; t < 2; t++) {
            const int cq = lcq0 + t;
            cp16(base + swz(lrow, cq), Vt + (size_t)lrow * 1024 + k0 + cq * 8);
        }
        asm volatile("cp.async.commit_group;");
    };
    #pragma unroll
    for (int i = 0; i < 4; i++) issue_vt(i, i);

    // ---- phase A: per-row max & sum ----
    float* sm_m = (float*)(smem + PV_MOFF);
    float* sm_i = sm_m + 128;
    #pragma unroll 1
    for (int r16 = 0; r16 < 16; r16++) {
        const int row = wid + r16 * 8;
        const uint4* rp = (const uint4*)(S + (size_t)row * 1024);
        uint4 u[4];
        #pragma unroll
        for (int i = 0; i < 4; i++) u[i] = rp[lane + i * 32];
        float m = -3.0e38f;
        #pragma unroll
        for (int i = 0; i < 4; i++) {
            const __half2* h = (const __half2*)&u[i];
            #pragma unroll
            for (int j = 0; j < 4; j++) {
                m = fmaxf(m, __low2float(h[j]));
                m = fmaxf(m, __high2float(h[j]));
            }
        }
        #pragma unroll
        for (int o = 16; o > 0; o >>= 1)
            m = fmaxf(m, __shfl_xor_sync(0xffffffffu, m, o));
        float s = 0.f;
        #pragma unroll
        for (int i = 0; i < 4; i++) {
            const __half2* h = (const __half2*)&u[i];
            #pragma unroll
            for (int j = 0; j < 4; j++) {
                s += __expf(__low2float(h[j]) - m);
                s += __expf(__high2float(h[j]) - m);
            }
        }
        #pragma unroll
        for (int o = 16; o > 0; o >>= 1)
            s += __shfl_xor_sync(0xffffffffu, s, o);
        if (lane == 0) { sm_m[row] = m; sm_i[row] = 1.f / s; }
    }
    __syncthreads();
    const float m_r = sm_m[lrow];
    const float i_r = sm_i[lrow];

    // ---- phase B ----
    float acc[2][8][4];
    #pragma unroll
    for (int mt = 0; mt < 2; mt++)
        #pragma unroll
        for (int nt = 0; nt < 8; nt++)
            #pragma unroll
            for (int j = 0; j < 4; j++)
                acc[mt][nt][j] = 0.f;

    const int frow = lane & 15;
    const int fhi  = lane >> 4;

    uint4 sreg[2];
    auto load_scores = [&](int s) {
        #pragma unroll
        for (int t = 0; t < 2; t++) {
            const int cq = lcq0 + t;
            sreg[t] = *(const uint4*)(S + (size_t)lrow * 1024 + (s << 5) + cq * 8);
        }
    };
    load_scores(0);

    int buf = 0;
    for (int s = 0; s < PV_NS; s++) {
        const int k0 = s << 5;
        // transform stage s: exp, weights write, pack to SMEM P buffer
        const uint32_t pbase = PV_PBUF + (uint32_t)(s & 1) * 8192;
        #pragma unroll
        for (int t = 0; t < 2; t++) {
            const int cq = lcq0 + t;
            const __half2* h = (const __half2*)&sreg[t];
            float v[8];
            #pragma unroll
            for (int j = 0; j < 4; j++) {
                v[2 * j]     = __expf(__low2float(h[j]) - m_r) * i_r;
                v[2 * j + 1] = __expf(__high2float(h[j]) - m_r) * i_r;
            }
            float* wp = wf + (size_t)lrow * 1024 + k0 + cq * 8;
            *(float4*)(wp)     = make_float4(v[0], v[1], v[2], v[3]);
            *(float4*)(wp + 4) = make_float4(v[4], v[5], v[6], v[7]);
            uint4 pk;
            pk.x = round2h(v[0], v[1]);
            pk.y = round2h(v[2], v[3]);
            pk.z = round2h(v[4], v[5]);
            pk.w = round2h(v[6], v[7]);
            *(uint4*)(smem + pbase + swz(lrow, cq)) = pk;
        }
        if (s + 1 < PV_NS) load_scores(s + 1);

        asm volatile("cp.async.wait_group 3;");
        __syncthreads();
        {
            const int nb = (buf + 4 >= NBUF) ? buf - 1 : buf + 4;
            if (s + 4 < PV_NS) issue_vt(s + 4, nb);
            else asm volatile("cp.async.commit_group;");
        }

        const uint32_t stb = sb + buf * 8192;
        const uint32_t pb  = sb + pbase;
        #pragma unroll
        for (int kq = 0; kq < 2; kq++) {
            uint32_t aH[2][4];
            #pragma unroll
            for (int mt = 0; mt < 2; mt++) {
                const int row = warpM * 32 + mt * 16 + frow;
                ldm_x4(aH[mt], pb + swz(row, kq * 2 + fhi));
            }
            #pragma unroll
            for (int half = 0; half < 2; half++) {
                uint32_t bH[2][4];
                #pragma unroll
                for (int g = 0; g < 2; g++) {
                    const int row = warpN * 64 + (half * 2 + g) * 16 + frow;
                    ldm_x4(bH[g], stb + swz(row, kq * 2 + fhi));
                }
                #pragma unroll
                for (int mt = 0; mt < 2; mt++)
                    #pragma unroll
                    for (int t4 = 0; t4 < 4; t4++) {
                        const int g = t4 >> 1, rs = t4 & 1;
                        mma16816(acc[mt][half * 4 + t4], aH[mt],
                                 bH[g][rs], bH[g][rs + 2]);
                    }
            }
        }
        if (++buf == NBUF) buf = 0;
    }
    __syncthreads();

    // epilogue: attn fp16 out
    {
        const int PITCH = 132;
        float* st = (float*)smem;
        const int tr = lane >> 2;
        const int tc = (lane & 3) * 2;
        #pragma unroll
        for (int mt = 0; mt < 2; mt++)
            #pragma unroll
            for (int nt = 0; nt < 8; nt++) {
                const int r0 = warpM * 32 + mt * 16 + tr;
                const int c0 = warpN * 64 + nt * 8 + tc;
                st[r0 * PITCH + c0]           = acc[mt][nt][0];
                st[r0 * PITCH + c0 + 1]       = acc[mt][nt][1];
                st[(r0 + 8) * PITCH + c0]     = acc[mt][nt][2];
                st[(r0 + 8) * PITCH + c0 + 1] = acc[mt][nt][3];
            }
        __syncthreads();

        const int orow = tid >> 1;
        const int ocb  = (tid & 1) * 64;
        const float* src = st + orow * PITCH + ocb;
        const size_t cbase = (size_t)orow * 128 + ocb;
        #pragma unroll
        for (int j = 0; j < 64; j += 2)
            *(uint32_t*)(Oh + cbase + j) = round2h(src[j], src[j + 1]);
    }
}

// ------------------------- aux kernels --------------------------------------

__global__ __launch_bounds__(256)
void round3_kernel(const float* __restrict__ x0, f16* __restrict__ h0,
                   const float* __restrict__ x1, f16* __restrict__ h1,
                   const float* __restrict__ x2, f16* __restrict__ h2)
{
    const float* x; f16* h;
    if (blockIdx.z == 0)      { x = x0; h = h0; }
    else if (blockIdx.z == 1) { x = x1; h = h1; }
    else                      { x = x2; h = h2; }
    const long long i = (long long)blockIdx.x * 256 + threadIdx.x;
    const float4 v = ((const float4*)x)[i];
    uint2 hu;
    hu.x = round2h(v.x, v.y);
    hu.y = round2h(v.z, v.w);
    ((uint2*)h)[i] = hu;
}

__global__ __launch_bounds__(256)
void round4_kernel(const float* __restrict__ x0, f16* __restrict__ h0,
                   const float* __restrict__ x1, f16* __restrict__ h1,
                   const float* __restrict__ x2, f16* __restrict__ h2,
                   const float* __restrict__ x3, f16* __restrict__ h3)
{
    const float* x; f16* h;
    if (blockIdx.z == 0)      { x = x0; h = h0; }
    else if (blockIdx.z == 1) { x = x1; h = h1; }
    else if (blockIdx.z == 2) { x = x2; h = h2; }
    else                      { x = x3; h = h3; }
    const long long i = (long long)blockIdx.x * 256 + threadIdx.x;
    const float4 v = ((const float4*)x)[i];
    uint2 hu;
    hu.x = round2h(v.x, v.y);
    hu.y = round2h(v.z, v.w);
    ((uint2*)h)[i] = hu;
}

// per-slab [1024,128] -> [128,1024] transpose of fp16 V
__global__ __launch_bounds__(256)
void transpose_v(const f16* __restrict__ vh, f16* __restrict__ vth)
{
    __shared__ f16 th[32][33];
    const int g = blockIdx.z;
    const int d0 = blockIdx.x * 32;
    const int k0 = blockIdx.y * 32;
    const size_t ib = (size_t)g * 131072;
    const int tx = threadIdx.x & 31;
    const int ty = threadIdx.x >> 5;
    #pragma unroll
    for (int i = 0; i < 4; i++) {
        const int k = k0 + ty + i * 8;
        th[ty + i * 8][tx] = vh[ib + (size_t)k * 128 + d0 + tx];
    }
    __syncthreads();
    #pragma unroll
    for (int i = 0; i < 4; i++) {
        const int d = d0 + ty + i * 8;
        vth[ib + (size_t)d * 1024 + k0 + tx] = th[tx][ty + i * 8];
    }
}

// ------------------------- launcher -----------------------------------------

extern "C" void kernel_launch(void* const* d_in, const int* in_sizes, int n_in,
                              void* d_out, int out_size)
{
    (void)in_sizes; (void)n_in;
    const float* query = (const float*)d_in[0];
    const float* key   = (const float*)d_in[1];
    const float* value = (const float*)d_in[2];
    const float* Wq_w  = (const float*)d_in[3];
    const float* Wq_b  = (const float*)d_in[4];
    const float* Wk_w  = (const float*)d_in[5];
    const float* Wk_b  = (const float*)d_in[6];
    const float* Wv_w  = (const float*)d_in[7];
    const float* Wv_b  = (const float*)d_in[8];
    const float* Wo_w  = (const float*)d_in[9];
    const float* Wo_b  = (const float*)d_in[10];

    f16 *xq, *xk, *xv, *wq, *wk, *wv, *wo;
    f16 *Qh, *Kh, *Vh, *Vth, *P, *Ahb;
    float* WS;
    cudaGetSymbolAddress((void**)&xq, g_xq);   cudaGetSymbolAddress((void**)&xk, g_xk);
    cudaGetSymbolAddress((void**)&xv, g_xv);
    cudaGetSymbolAddress((void**)&wq, g_wq);   cudaGetSymbolAddress((void**)&wk, g_wk);
    cudaGetSymbolAddress((void**)&wv, g_wv);   cudaGetSymbolAddress((void**)&wo, g_wo);
    cudaGetSymbolAddress((void**)&Qh, g_Qh);   cudaGetSymbolAddress((void**)&Kh, g_Kh);
    cudaGetSymbolAddress((void**)&Vh, g_Vh);   cudaGetSymbolAddress((void**)&Vth, g_Vth);
    cudaGetSymbolAddress((void**)&P, g_P);     cudaGetSymbolAddress((void**)&Ahb, g_Ah);
    cudaGetSymbolAddress((void**)&WS, g_WS);

    float* out = (float*)d_out;
    float* weights = ((long long)out_size >= QKV_ELEMS + W_ELEMS)
                         ? out + QKV_ELEMS : WS;

    cudaFuncSetAttribute(gemm_mma<0>, cudaFuncAttributeMaxDynamicSharedMemorySize, SMEM_TOTAL);
    cudaFuncSetAttribute(gemm_mma<1>, cudaFuncAttributeMaxDynamicSharedMemorySize, SMEM_TOTAL);
    cudaFuncSetAttribute(gemm_mma<3>, cudaFuncAttributeMaxDynamicSharedMemorySize, SMEM_TOTAL);
    cudaFuncSetAttribute(attn_pv, cudaFuncAttributeMaxDynamicSharedMemorySize, PV_SMEM);

    const float inv_sqrt_d = 0.022097086912079608f;  // 1/sqrt(2048)
    dim3 blk(256);

    // preprocessing rounds
    round3_kernel<<<dim3(16384, 1, 3), blk>>>(query, xq, key, xk, value, xv);
    round4_kernel<<<dim3(4096, 1, 4), blk>>>(Wq_w, wq, Wk_w, wk, Wv_w, wv, Wo_w, wo);

    // fused Q/K/V projections: one GEMM, x-grid selects {Q,K,V}
    gemm_mma<0><<<dim3(48, 64, 1), blk, SMEM_TOTAL>>>(
        xq, xk, xv, wq, wk, wv, Wq_b, Wk_b, Wv_b,
        nullptr, Qh, Kh, Vh,
        2048, 2048, 2048, 2048, 0, 0, 0, 1.f);

    transpose_v<<<dim3(4, 32, 128), blk>>>(Vh, Vth);

    // scores = Q K^T * scale per contiguous slab -> fp16 scores buffer
    gemm_mma<1><<<dim3(8, 8, 128), blk, SMEM_TOTAL>>>(
        Qh, nullptr, nullptr, Kh, nullptr, nullptr, nullptr, nullptr, nullptr,
        nullptr, P, nullptr, nullptr,
        128, 128, 128, 1024,
        131072LL, 131072LL, 1048576LL, inv_sqrt_d);

    // fused softmax + PV: fp32 weights out + fp16 attn out
    attn_pv<<<dim3(1, 8, 128), blk, PV_SMEM>>>(P, Vth, weights, Ahb);

    // out = attn Wo^T + b -> fp32
    gemm_mma<3><<<dim3(16, 64, 1), blk, SMEM_TOTAL>>>(
        Ahb, nullptr, nullptr, wo, nullptr, nullptr, Wo_b, nullptr, nullptr,
        out, nullptr, nullptr, nullptr,
        2048, 2048, 2048, 2048, 0, 0, 0, 1.f);
}